// round 1
// baseline (speedup 1.0000x reference)
#include <cuda_runtime.h>
#include <math.h>

// Problem constants
#define NNODES 768
#define CF     1024      // feats dim
#define HCH    256       // hidden of rel MLP
#define KNB    21        // K=20 + self
#define XDIM   1028      // C + 4

// ---------------- scratch (device globals; no allocation allowed) ----------------
__device__ float g_X[NNODES * XDIM];        // [feats | geom]
__device__ float g_Bcat[1024 * 512];        // [Wa | Wb]
__device__ float g_fafb[NNODES * 512];      // fa (0..255) | fb (256..511)
__device__ float g_rel[NNODES * NNODES];
__device__ int   g_nbr[NNODES * KNB];
__device__ float g_xp[NNODES * 1024];
__device__ float g_asrc[NNODES * 4];
__device__ float g_adst[NNODES * 4];
__device__ float g_h1[NNODES * 1024];
__device__ float g_regin[NNODES * XDIM];    // [h1 | geom]
__device__ float g_hid[NNODES * 128];
__device__ float g_xp2[NNODES * 2];
__device__ float g_a2s[NNODES];
__device__ float g_a2d[NNODES];

// ---------------- pack: X = [feats|geom], Bcat = [Wa|Wb] ----------------
__global__ void pack_kernel(const float* __restrict__ feats,
                            const float* __restrict__ boxes,
                            const float* __restrict__ W1) {
    int t = blockIdx.x * 256 + threadIdx.x;
    int stride = gridDim.x * 256;
    const float inv800 = 1.0f / 800.0f;
    for (int idx = t; idx < NNODES * XDIM; idx += stride) {
        int n = idx / XDIM, c = idx - n * XDIM;
        g_X[idx] = (c < CF) ? feats[n * CF + c] : boxes[n * 4 + (c - CF)] * inv800;
    }
    for (int idx = t; idx < 1024 * 512; idx += stride) {
        int k = idx >> 9, j = idx & 511;
        g_Bcat[idx] = (j < 256) ? W1[k * 256 + j] : W1[(1024 + k) * 256 + (j - 256)];
    }
}

// ---------------- generic tiled SGEMM: C = A(MxK) * B(KxN) [+bias][relu] ----------------
template<int BM, int BN, int BK, int TM, int TN>
__global__ void sgemm(const float* __restrict__ A, const float* __restrict__ B,
                      float* __restrict__ Cmat, int M, int Kd, int Nn,
                      int lda, int ldb, int ldc,
                      const float* __restrict__ bias, int do_relu) {
    __shared__ float As[BK][BM + 1];
    __shared__ float Bs[BK][BN];
    const int tid = threadIdx.x;              // 256 threads
    const int tcols = BN / TN;
    const int tx = tid % tcols;
    const int ty = tid / tcols;
    const int row0 = blockIdx.y * BM;
    const int col0 = blockIdx.x * BN;

    float acc[TM][TN];
    #pragma unroll
    for (int i = 0; i < TM; i++)
        #pragma unroll
        for (int j = 0; j < TN; j++) acc[i][j] = 0.0f;

    for (int k0 = 0; k0 < Kd; k0 += BK) {
        // A tile (BM x BK), one float4 per thread per slice
        #pragma unroll
        for (int l = 0; l < (BM * BK) / (256 * 4); l++) {
            int e  = tid + l * 256;
            int ar = e / (BK / 4);
            int ac = (e % (BK / 4)) * 4;
            int gk = k0 + ac;
            float4 v;
            if (gk + 3 < Kd) {
                v = *(const float4*)(A + (size_t)(row0 + ar) * lda + gk);
            } else {
                float t0 = (gk + 0 < Kd) ? A[(size_t)(row0 + ar) * lda + gk + 0] : 0.f;
                float t1 = (gk + 1 < Kd) ? A[(size_t)(row0 + ar) * lda + gk + 1] : 0.f;
                float t2 = (gk + 2 < Kd) ? A[(size_t)(row0 + ar) * lda + gk + 2] : 0.f;
                float t3 = (gk + 3 < Kd) ? A[(size_t)(row0 + ar) * lda + gk + 3] : 0.f;
                v = make_float4(t0, t1, t2, t3);
            }
            As[ac + 0][ar] = v.x; As[ac + 1][ar] = v.y;
            As[ac + 2][ar] = v.z; As[ac + 3][ar] = v.w;
        }
        // B tile (BK x BN)
        #pragma unroll
        for (int l = 0; l < (BK * BN) / (256 * 4); l++) {
            int e  = tid + l * 256;
            int br = e / (BN / 4);
            int bc = (e % (BN / 4)) * 4;
            float4 v = make_float4(0.f, 0.f, 0.f, 0.f);
            if (k0 + br < Kd)
                v = *(const float4*)(B + (size_t)(k0 + br) * ldb + col0 + bc);
            *(float4*)(&Bs[br][bc]) = v;
        }
        __syncthreads();
        #pragma unroll
        for (int k = 0; k < BK; k++) {
            float ra[TM], rb[TN];
            #pragma unroll
            for (int i = 0; i < TM; i++) ra[i] = As[k][ty * TM + i];
            #pragma unroll
            for (int j = 0; j < TN; j++) rb[j] = Bs[k][tx * TN + j];
            #pragma unroll
            for (int i = 0; i < TM; i++)
                #pragma unroll
                for (int j = 0; j < TN; j++)
                    acc[i][j] = fmaf(ra[i], rb[j], acc[i][j]);
        }
        __syncthreads();
    }
    #pragma unroll
    for (int i = 0; i < TM; i++) {
        int r = row0 + ty * TM + i;
        #pragma unroll
        for (int j = 0; j < TN; j++) {
            int c = col0 + tx * TN + j;
            float v = acc[i][j];
            if (bias) v += bias[c];
            if (do_relu) v = fmaxf(v, 0.0f);
            Cmat[(size_t)r * ldc + c] = v;
        }
    }
}

// ---------------- fused pairwise relation score ----------------
// rel[i,j] = sum_h relu(fa_i[h] + fb_j[h] + |box_i - box_j| . Wg[:,h] + b1[h]) * W2[h] + b2
__global__ void rel_kernel(const float* __restrict__ boxes,
                           const float* __restrict__ W1,
                           const float* __restrict__ b1,
                           const float* __restrict__ W2,
                           const float* __restrict__ b2,
                           float* __restrict__ rel) {
    __shared__ float fa_s[32 * 128];
    __shared__ float fb_s[32 * 129];
    __shared__ float4 wg_s[128];
    __shared__ float w2_s[128];
    __shared__ float bb_s[256];   // 32 i-boxes then 32 j-boxes (4 each)

    const int i0 = blockIdx.y * 32, j0 = blockIdx.x * 32;
    const int tx = threadIdx.x, ty = threadIdx.y;
    const int tid = ty * 32 + tx;

    if (tid < 128) { bb_s[tid] = boxes[i0 * 4 + tid]; bb_s[128 + tid] = boxes[j0 * 4 + tid]; }
    __syncthreads();

    float bj0 = bb_s[128 + tx * 4 + 0], bj1 = bb_s[128 + tx * 4 + 1];
    float bj2 = bb_s[128 + tx * 4 + 2], bj3 = bb_s[128 + tx * 4 + 3];
    float d[4][4];
    #pragma unroll
    for (int r = 0; r < 4; r++) {
        int ii = ty * 4 + r;
        d[r][0] = fabsf(bb_s[ii * 4 + 0] - bj0);
        d[r][1] = fabsf(bb_s[ii * 4 + 1] - bj1);
        d[r][2] = fabsf(bb_s[ii * 4 + 2] - bj2);
        d[r][3] = fabsf(bb_s[ii * 4 + 3] - bj3);
    }

    float acc[4] = {0.f, 0.f, 0.f, 0.f};
    for (int c0 = 0; c0 < 256; c0 += 128) {
        __syncthreads();
        for (int t = tid; t < 32 * 128; t += 256) {
            int r = t >> 7, h = t & 127;
            fa_s[r * 128 + h] = g_fafb[(size_t)(i0 + r) * 512 + c0 + h] + b1[c0 + h];
            fb_s[r * 129 + h] = g_fafb[(size_t)(j0 + r) * 512 + 256 + c0 + h];
        }
        if (tid < 128) {
            int h = c0 + tid;
            wg_s[tid] = make_float4(W1[2048 * 256 + h], W1[2049 * 256 + h],
                                    W1[2050 * 256 + h], W1[2051 * 256 + h]);
            w2_s[tid] = W2[h];
        }
        __syncthreads();
        #pragma unroll 2
        for (int h = 0; h < 128; h++) {
            float4 wg = wg_s[h];
            float fbv = fb_s[tx * 129 + h];
            float w2v = w2_s[h];
            #pragma unroll
            for (int r = 0; r < 4; r++) {
                float g = fmaf(d[r][0], wg.x,
                          fmaf(d[r][1], wg.y,
                          fmaf(d[r][2], wg.z, d[r][3] * wg.w)));
                float t = fa_s[(ty * 4 + r) * 128 + h] + fbv + g;
                t = fmaxf(t, 0.0f);
                acc[r] = fmaf(t, w2v, acc[r]);
            }
        }
    }
    float b2v = b2[0];
    #pragma unroll
    for (int r = 0; r < 4; r++) {
        int i = i0 + ty * 4 + r, j = j0 + tx;
        float v = acc[r] + b2v;
        if (i == j) v = -1e9f;
        rel[(size_t)i * NNODES + j] = v;
    }
}

// ---------------- top-20 per row (+ self) ----------------
__global__ void topk_kernel(const float* __restrict__ rel, int* __restrict__ nbr) {
    __shared__ float vals[NNODES];
    __shared__ float rv[256];
    __shared__ int   ri[256];
    const int n = blockIdx.x, tid = threadIdx.x;
    for (int t = tid; t < NNODES; t += 256) vals[t] = rel[(size_t)n * NNODES + t];
    __syncthreads();
    for (int s = 0; s < 20; s++) {
        float best = -3.4e38f; int bi = NNODES;
        for (int t = tid; t < NNODES; t += 256) {
            float v = vals[t];
            if (v > best || (v == best && t < bi)) { best = v; bi = t; }
        }
        rv[tid] = best; ri[tid] = bi;
        __syncthreads();
        for (int off = 128; off > 0; off >>= 1) {
            if (tid < off) {
                if (rv[tid + off] > rv[tid] ||
                    (rv[tid + off] == rv[tid] && ri[tid + off] < ri[tid])) {
                    rv[tid] = rv[tid + off]; ri[tid] = ri[tid + off];
                }
            }
            __syncthreads();
        }
        if (tid == 0) { nbr[n * KNB + s] = ri[0]; vals[ri[0]] = -3.4e38f; }
        __syncthreads();
    }
    if (tid == 0) nbr[n * KNB + 20] = n;
}

// ---------------- GAT1 attention coefficients ----------------
__global__ void attn_coef_kernel(const float* __restrict__ g1as,
                                 const float* __restrict__ g1ad) {
    const int n = blockIdx.x, tid = threadIdx.x;    // 128 threads, warp per head
    const int h = tid >> 5, lane = tid & 31;
    float s = 0.f, ds = 0.f;
    for (int f = lane; f < 256; f += 32) {
        float x = g_xp[(size_t)n * 1024 + h * 256 + f];
        s  = fmaf(x, g1as[h * 256 + f], s);
        ds = fmaf(x, g1ad[h * 256 + f], ds);
    }
    #pragma unroll
    for (int o = 16; o > 0; o >>= 1) {
        s  += __shfl_down_sync(0xffffffffu, s, o);
        ds += __shfl_down_sync(0xffffffffu, ds, o);
    }
    if (lane == 0) { g_asrc[n * 4 + h] = s; g_adst[n * 4 + h] = ds; }
}

// ---------------- GAT1 aggregate -> h1, regin ----------------
__global__ void gat1_kernel(const float* __restrict__ g1b,
                            const float* __restrict__ boxes) {
    __shared__ float alpha[KNB * 4];
    __shared__ int nb[KNB];
    const int n = blockIdx.x, tid = threadIdx.x;    // 256 threads
    if (tid < KNB) nb[tid] = g_nbr[n * KNB + tid];
    __syncthreads();
    if (tid < 4) {
        int h = tid;
        float ad = g_adst[n * 4 + h];
        float lg[KNB]; float mx = -3.4e38f;
        for (int k = 0; k < KNB; k++) {
            float v = g_asrc[nb[k] * 4 + h] + ad;
            v = (v > 0.f) ? v : 0.2f * v;
            lg[k] = v; mx = fmaxf(mx, v);
        }
        float ssum = 0.f;
        for (int k = 0; k < KNB; k++) { lg[k] = expf(lg[k] - mx); ssum += lg[k]; }
        float inv = 1.0f / ssum;
        for (int k = 0; k < KNB; k++) alpha[k * 4 + h] = lg[k] * inv;
    }
    __syncthreads();
    #pragma unroll
    for (int r = 0; r < 4; r++) {
        int idx = tid + r * 256;
        int h = idx >> 8;
        float acc = 0.f;
        #pragma unroll
        for (int k = 0; k < KNB; k++)
            acc = fmaf(alpha[k * 4 + h], g_xp[(size_t)nb[k] * 1024 + idx], acc);
        float v = fmaxf(acc + g1b[idx], 0.0f);
        g_h1[(size_t)n * 1024 + idx] = v;
        g_regin[(size_t)n * XDIM + idx] = v;
    }
    if (tid < 4) g_regin[(size_t)n * XDIM + 1024 + tid] = boxes[n * 4 + tid] * (1.0f / 800.0f);
}

// ---------------- GAT2 projection + coefficients ----------------
__global__ void gat2_proj_kernel(const float* __restrict__ g2W,
                                 const float* __restrict__ g2as,
                                 const float* __restrict__ g2ad) {
    __shared__ float s0[256], s1[256];
    const int n = blockIdx.x, tid = threadIdx.x;    // 256
    float a0 = 0.f, a1 = 0.f;
    for (int i = tid; i < 1024; i += 256) {
        float v = g_h1[(size_t)n * 1024 + i];
        a0 = fmaf(v, g2W[i * 2 + 0], a0);
        a1 = fmaf(v, g2W[i * 2 + 1], a1);
    }
    s0[tid] = a0; s1[tid] = a1;
    __syncthreads();
    for (int o = 128; o > 0; o >>= 1) {
        if (tid < o) { s0[tid] += s0[tid + o]; s1[tid] += s1[tid + o]; }
        __syncthreads();
    }
    if (tid == 0) {
        float x0 = s0[0], x1 = s1[0];
        g_xp2[n * 2 + 0] = x0; g_xp2[n * 2 + 1] = x1;
        g_a2s[n] = x0 * g2as[0] + x1 * g2as[1];
        g_a2d[n] = x0 * g2ad[0] + x1 * g2ad[1];
    }
}

// ---------------- final: GAT2 aggregate (logits) + reg head + box decode ----------------
__global__ void final_kernel(const float* __restrict__ g2b,
                             const float* __restrict__ rW2,
                             const float* __restrict__ rb2,
                             const float* __restrict__ boxes,
                             float* __restrict__ out) {
    __shared__ float delta[4];
    const int n = blockIdx.x, tid = threadIdx.x;    // 128 threads
    const int c = tid >> 5, lane = tid & 31;
    float acc = 0.f;
    for (int i = lane; i < 128; i += 32)
        acc = fmaf(g_hid[(size_t)n * 128 + i], rW2[i * 4 + c], acc);
    #pragma unroll
    for (int o = 16; o > 0; o >>= 1) acc += __shfl_down_sync(0xffffffffu, acc, o);
    if (lane == 0) delta[c] = acc + rb2[c];
    __syncthreads();
    if (tid == 0) {
        // GAT2 aggregate (heads=1, feat=2)
        float ad = g_a2d[n];
        float lg[KNB]; float mx = -3.4e38f;
        int nb[KNB];
        for (int k = 0; k < KNB; k++) nb[k] = g_nbr[n * KNB + k];
        for (int k = 0; k < KNB; k++) {
            float v = g_a2s[nb[k]] + ad;
            v = (v > 0.f) ? v : 0.2f * v;
            lg[k] = v; mx = fmaxf(mx, v);
        }
        float ssum = 0.f;
        for (int k = 0; k < KNB; k++) { lg[k] = expf(lg[k] - mx); ssum += lg[k]; }
        float inv = 1.0f / ssum;
        float o0 = 0.f, o1 = 0.f;
        for (int k = 0; k < KNB; k++) {
            float a = lg[k] * inv;
            o0 = fmaf(a, g_xp2[nb[k] * 2 + 0], o0);
            o1 = fmaf(a, g_xp2[nb[k] * 2 + 1], o1);
        }
        out[n * 6 + 0] = o0 + g2b[0];
        out[n * 6 + 1] = o1 + g2b[1];
        // box decode
        float x0 = boxes[n * 4 + 0], y0 = boxes[n * 4 + 1];
        float x1 = boxes[n * 4 + 2], y1 = boxes[n * 4 + 3];
        float pw = x1 - x0, ph = y1 - y0;
        float pcx = x0 + 0.5f * pw, pcy = y0 + 0.5f * ph;
        float gcx = delta[0] * pw + pcx, gcy = delta[1] * ph + pcy;
        float gw = expf(delta[2]) * pw, gh = expf(delta[3]) * ph;
        out[n * 6 + 2] = gcx - 0.5f * gw;
        out[n * 6 + 3] = gcy - 0.5f * gh;
        out[n * 6 + 4] = gcx + 0.5f * gw;
        out[n * 6 + 5] = gcy + 0.5f * gh;
    }
}

// ---------------- launch ----------------
extern "C" void kernel_launch(void* const* d_in, const int* in_sizes, int n_in,
                              void* d_out, int out_size) {
    const float* feats = (const float*)d_in[0];
    const float* boxes = (const float*)d_in[1];
    const float* W1    = (const float*)d_in[2];
    const float* b1    = (const float*)d_in[3];
    const float* W2    = (const float*)d_in[4];
    const float* b2    = (const float*)d_in[5];
    const float* g1W   = (const float*)d_in[6];
    const float* g1as  = (const float*)d_in[7];
    const float* g1ad  = (const float*)d_in[8];
    const float* g1b   = (const float*)d_in[9];
    const float* g2W   = (const float*)d_in[10];
    const float* g2as  = (const float*)d_in[11];
    const float* g2ad  = (const float*)d_in[12];
    const float* g2b   = (const float*)d_in[13];
    const float* rW1   = (const float*)d_in[14];
    const float* rb1   = (const float*)d_in[15];
    const float* rW2   = (const float*)d_in[16];
    const float* rb2   = (const float*)d_in[17];
    float* out = (float*)d_out;

    float *pX, *pBcat, *pFafb, *pRel, *pRegin, *pHid;
    int *pNbr;
    cudaGetSymbolAddress((void**)&pX,     g_X);
    cudaGetSymbolAddress((void**)&pBcat,  g_Bcat);
    cudaGetSymbolAddress((void**)&pFafb,  g_fafb);
    cudaGetSymbolAddress((void**)&pRel,   g_rel);
    cudaGetSymbolAddress((void**)&pNbr,   g_nbr);
    cudaGetSymbolAddress((void**)&pRegin, g_regin);
    cudaGetSymbolAddress((void**)&pHid,   g_hid);
    float* pXp; cudaGetSymbolAddress((void**)&pXp, g_xp);

    // 1. pack X and Bcat
    pack_kernel<<<256, 256>>>(feats, boxes, W1);

    // 2. fa|fb = feats @ [Wa|Wb]   (768 x 512 x 1024)
    sgemm<64, 64, 16, 4, 4><<<dim3(512 / 64, 768 / 64), 256>>>(
        feats, pBcat, pFafb, NNODES, 1024, 512, 1024, 512, 512, nullptr, 0);

    // 3. pairwise relation scores
    rel_kernel<<<dim3(24, 24), dim3(32, 8)>>>(boxes, W1, b1, W2, b2, pRel);

    // 4. top-K neighbors
    topk_kernel<<<NNODES, 256>>>(pRel, pNbr);

    // 5. xp = X @ g1W   (768 x 1024 x 1028)
    sgemm<64, 64, 16, 4, 4><<<dim3(1024 / 64, 768 / 64), 256>>>(
        pX, g1W, pXp, NNODES, XDIM, 1024, XDIM, 1024, 1024, nullptr, 0);

    // 6. GAT1 attention coefficients
    attn_coef_kernel<<<NNODES, 128>>>(g1as, g1ad);

    // 7. GAT1 aggregate -> h1, regin
    gat1_kernel<<<NNODES, 256>>>(g1b, boxes);

    // 8. hid = relu(regin @ rW1 + rb1)   (768 x 128 x 1028)
    sgemm<32, 32, 32, 2, 2><<<dim3(128 / 32, 768 / 32), 256>>>(
        pRegin, rW1, pHid, NNODES, XDIM, 128, XDIM, 128, 128, rb1, 1);

    // 9. GAT2 projection + coefficients
    gat2_proj_kernel<<<NNODES, 256>>>(g2W, g2as, g2ad);

    // 10. final: GAT2 aggregate + regression + decode
    final_kernel<<<NNODES, 128>>>(g2b, rW2, rb2, boxes, out);
}

// round 2
// speedup vs baseline: 1.6411x; 1.6411x over previous
#include <cuda_runtime.h>
#include <math.h>

// Problem constants
#define NNODES 768
#define CF     1024
#define KNB    21        // K=20 + self
#define XD     1028      // C + 4 (logical)
#define XP     1056      // padded K (multiple of 16)

// ---------------- scratch (device globals) ----------------
__device__ float g_X[NNODES * XP];          // [feats | geom | 0pad]
__device__ float g_Bcat[1024 * 512];        // [Wa | Wb]
__device__ float g_W1p[XP * 1024];          // g1W zero-padded rows
__device__ float g_rW1p[XP * 128];          // rW1 zero-padded rows
__device__ float g_fafb[NNODES * 512];      // fa | fb
__device__ float g_rel[NNODES * NNODES];
__device__ int   g_nbr[NNODES * KNB];
__device__ float g_xp[NNODES * 1024];
__device__ float g_asrc[NNODES * 4];
__device__ float g_adst[NNODES * 4];
__device__ float g_h1[NNODES * 1024];
__device__ float g_regin[NNODES * XP];      // [h1 | geom | 0pad]
__device__ float g_hid[NNODES * 128];
__device__ float g_xp2[NNODES * 2];
__device__ float g_a2s[NNODES];
__device__ float g_a2d[NNODES];

// ---------------- pack / pad ----------------
__global__ void pack_kernel(const float* __restrict__ feats,
                            const float* __restrict__ boxes,
                            const float* __restrict__ W1,
                            const float* __restrict__ g1W,
                            const float* __restrict__ rW1) {
    int t = blockIdx.x * 256 + threadIdx.x;
    int stride = gridDim.x * 256;
    const float inv800 = 1.0f / 800.0f;
    // X = [feats | geom | 0]
    for (int idx = t; idx < NNODES * XP; idx += stride) {
        int n = idx / XP, c = idx - n * XP;
        float v;
        if (c < CF)        v = feats[n * CF + c];
        else if (c < XD)   v = boxes[n * 4 + (c - CF)] * inv800;
        else               v = 0.0f;
        g_X[idx] = v;
    }
    // Bcat = [Wa | Wb]
    for (int idx = t; idx < 1024 * 512; idx += stride) {
        int k = idx >> 9, j = idx & 511;
        g_Bcat[idx] = (j < 256) ? W1[k * 256 + j] : W1[(1024 + k) * 256 + (j - 256)];
    }
    // padded g1W
    for (int idx = t; idx < XP * 1024; idx += stride) {
        int k = idx >> 10, j = idx & 1023;
        g_W1p[idx] = (k < XD) ? g1W[k * 1024 + j] : 0.0f;
    }
    // padded rW1
    for (int idx = t; idx < XP * 128; idx += stride) {
        int k = idx >> 7, j = idx & 127;
        g_rW1p[idx] = (k < XD) ? rW1[k * 128 + j] : 0.0f;
    }
    // regin K-pad zeros (cols 1028..1055)
    for (int idx = t; idx < NNODES * (XP - XD); idx += stride) {
        int n = idx / (XP - XD), c = idx % (XP - XD);
        g_regin[n * XP + XD + c] = 0.0f;
    }
}

// ---------------- 64x64x16 SGEMM body (reg-prefetch double buffer) ----------------
__device__ __forceinline__ void sgemm_body(const float* __restrict__ A,
                                           const float* __restrict__ B,
                                           float* __restrict__ C,
                                           int K, int lda, int ldb, int ldc,
                                           int row0, int col0) {
    __shared__ float As[16][68];   // 68 keeps float4 alignment (272B rows)
    __shared__ float Bs[16][64];
    const int tid  = threadIdx.x;
    const int arow = tid >> 2, akq = (tid & 3) << 2;
    const int brow = tid >> 4, bcol = (tid & 15) << 2;
    const int tx = tid & 15, ty = tid >> 4;

    float4 aR = *(const float4*)(A + (row0 + arow) * lda + akq);
    float4 bR = *(const float4*)(B + brow * ldb + col0 + bcol);

    float acc[4][4];
    #pragma unroll
    for (int i = 0; i < 4; i++)
        #pragma unroll
        for (int j = 0; j < 4; j++) acc[i][j] = 0.0f;

    for (int k0 = 0; k0 < K; k0 += 16) {
        As[akq + 0][arow] = aR.x; As[akq + 1][arow] = aR.y;
        As[akq + 2][arow] = aR.z; As[akq + 3][arow] = aR.w;
        *(float4*)(&Bs[brow][bcol]) = bR;
        __syncthreads();
        if (k0 + 16 < K) {
            aR = *(const float4*)(A + (row0 + arow) * lda + k0 + 16 + akq);
            bR = *(const float4*)(B + (k0 + 16 + brow) * ldb + col0 + bcol);
        }
        #pragma unroll
        for (int k = 0; k < 16; k++) {
            float4 a = *(const float4*)(&As[k][ty << 2]);
            float4 b = *(const float4*)(&Bs[k][tx << 2]);
            acc[0][0] = fmaf(a.x, b.x, acc[0][0]);
            acc[0][1] = fmaf(a.x, b.y, acc[0][1]);
            acc[0][2] = fmaf(a.x, b.z, acc[0][2]);
            acc[0][3] = fmaf(a.x, b.w, acc[0][3]);
            acc[1][0] = fmaf(a.y, b.x, acc[1][0]);
            acc[1][1] = fmaf(a.y, b.y, acc[1][1]);
            acc[1][2] = fmaf(a.y, b.z, acc[1][2]);
            acc[1][3] = fmaf(a.y, b.w, acc[1][3]);
            acc[2][0] = fmaf(a.z, b.x, acc[2][0]);
            acc[2][1] = fmaf(a.z, b.y, acc[2][1]);
            acc[2][2] = fmaf(a.z, b.z, acc[2][2]);
            acc[2][3] = fmaf(a.z, b.w, acc[2][3]);
            acc[3][0] = fmaf(a.w, b.x, acc[3][0]);
            acc[3][1] = fmaf(a.w, b.y, acc[3][1]);
            acc[3][2] = fmaf(a.w, b.z, acc[3][2]);
            acc[3][3] = fmaf(a.w, b.w, acc[3][3]);
        }
        __syncthreads();
    }
    #pragma unroll
    for (int i = 0; i < 4; i++) {
        float4 o = make_float4(acc[i][0], acc[i][1], acc[i][2], acc[i][3]);
        *(float4*)(C + (row0 + (ty << 2) + i) * ldc + col0 + (tx << 2)) = o;
    }
}

// ---------------- mega GEMM: fafb (96 blocks) + xp (192 blocks) in one launch ----------------
__global__ __launch_bounds__(256) void mega_gemm(const float* __restrict__ feats) {
    int blk = blockIdx.x;
    if (blk < 96) {
        // fafb = feats[768x1024] @ Bcat[1024x512]
        int bx = blk & 7, by = blk >> 3;
        sgemm_body(feats, g_Bcat, g_fafb, 1024, 1024, 512, 512, by * 64, bx * 64);
    } else {
        // xp = X[768xXP] @ W1p[XPx1024]
        blk -= 96;
        int bx = blk & 15, by = blk >> 4;
        sgemm_body(g_X, g_W1p, g_xp, XP, XP, 1024, 1024, by * 64, bx * 64);
    }
}

// ---------------- fused pairwise relation score ----------------
__global__ void rel_kernel(const float* __restrict__ boxes,
                           const float* __restrict__ W1,
                           const float* __restrict__ b1,
                           const float* __restrict__ W2,
                           const float* __restrict__ b2,
                           float* __restrict__ rel) {
    __shared__ float fa_s[32 * 128];
    __shared__ float fb_s[32 * 129];
    __shared__ float4 wg_s[128];
    __shared__ float w2_s[128];
    __shared__ float bb_s[256];

    const int i0 = blockIdx.y * 32, j0 = blockIdx.x * 32;
    const int tx = threadIdx.x, ty = threadIdx.y;
    const int tid = ty * 32 + tx;

    if (tid < 128) { bb_s[tid] = boxes[i0 * 4 + tid]; bb_s[128 + tid] = boxes[j0 * 4 + tid]; }
    __syncthreads();

    float bj0 = bb_s[128 + tx * 4 + 0], bj1 = bb_s[128 + tx * 4 + 1];
    float bj2 = bb_s[128 + tx * 4 + 2], bj3 = bb_s[128 + tx * 4 + 3];
    float d[4][4];
    #pragma unroll
    for (int r = 0; r < 4; r++) {
        int ii = ty * 4 + r;
        d[r][0] = fabsf(bb_s[ii * 4 + 0] - bj0);
        d[r][1] = fabsf(bb_s[ii * 4 + 1] - bj1);
        d[r][2] = fabsf(bb_s[ii * 4 + 2] - bj2);
        d[r][3] = fabsf(bb_s[ii * 4 + 3] - bj3);
    }

    float acc[4] = {0.f, 0.f, 0.f, 0.f};
    for (int c0 = 0; c0 < 256; c0 += 128) {
        __syncthreads();
        for (int t = tid; t < 32 * 128; t += 256) {
            int r = t >> 7, h = t & 127;
            fa_s[r * 128 + h] = g_fafb[(i0 + r) * 512 + c0 + h] + b1[c0 + h];
            fb_s[r * 129 + h] = g_fafb[(j0 + r) * 512 + 256 + c0 + h];
        }
        if (tid < 128) {
            int h = c0 + tid;
            wg_s[tid] = make_float4(W1[2048 * 256 + h], W1[2049 * 256 + h],
                                    W1[2050 * 256 + h], W1[2051 * 256 + h]);
            w2_s[tid] = W2[h];
        }
        __syncthreads();
        #pragma unroll 2
        for (int h = 0; h < 128; h++) {
            float4 wg = wg_s[h];
            float fbv = fb_s[tx * 129 + h];
            float w2v = w2_s[h];
            #pragma unroll
            for (int r = 0; r < 4; r++) {
                float g = fmaf(d[r][0], wg.x,
                          fmaf(d[r][1], wg.y,
                          fmaf(d[r][2], wg.z, d[r][3] * wg.w)));
                float t = fa_s[(ty * 4 + r) * 128 + h] + fbv + g;
                t = fmaxf(t, 0.0f);
                acc[r] = fmaf(t, w2v, acc[r]);
            }
        }
    }
    float b2v = b2[0];
    #pragma unroll
    for (int r = 0; r < 4; r++) {
        int i = i0 + ty * 4 + r, j = j0 + tx;
        float v = acc[r] + b2v;
        if (i == j) v = -1e9f;
        rel[i * NNODES + j] = v;
    }
}

// ---------------- top-20 per row: one warp per row, values in registers ----------------
__global__ void topk_warp(const float* __restrict__ rel, int* __restrict__ nbr) {
    const int warp = (blockIdx.x * blockDim.x + threadIdx.x) >> 5;
    const int lane = threadIdx.x & 31;
    if (warp >= NNODES) return;
    const float* row = rel + warp * NNODES;
    float v[24];
    #pragma unroll
    for (int m = 0; m < 24; m++) v[m] = row[m * 32 + lane];
    unsigned removed = 0;
    for (int s = 0; s < 20; s++) {
        float best = -3.4e38f; int bm = -1;
        #pragma unroll
        for (int m = 0; m < 24; m++) {
            bool alive = ((removed >> m) & 1u) == 0u;
            if (alive && v[m] > best) { best = v[m]; bm = m; }
        }
        int bidx = (bm >= 0) ? (bm * 32 + lane) : (1 << 20);
        #pragma unroll
        for (int o = 16; o > 0; o >>= 1) {
            float ov = __shfl_xor_sync(0xffffffffu, best, o);
            int   oi = __shfl_xor_sync(0xffffffffu, bidx, o);
            if (ov > best || (ov == best && oi < bidx)) { best = ov; bidx = oi; }
        }
        if (lane == (bidx & 31)) removed |= 1u << (bidx >> 5);
        if (lane == 0) nbr[warp * KNB + s] = bidx;
    }
    if (lane == 0) nbr[warp * KNB + 20] = warp;
}

// ---------------- GAT1 attention coefficients ----------------
__global__ void attn_coef_kernel(const float* __restrict__ g1as,
                                 const float* __restrict__ g1ad) {
    const int n = blockIdx.x, tid = threadIdx.x;    // 128 threads, warp per head
    const int h = tid >> 5, lane = tid & 31;
    float s = 0.f, ds = 0.f;
    #pragma unroll
    for (int f0 = 0; f0 < 256; f0 += 128) {
        int f = f0 + lane * 4;
        float4 x = *(const float4*)&g_xp[n * 1024 + h * 256 + f];
        float4 ws = *(const float4*)&g1as[h * 256 + f];
        float4 wd = *(const float4*)&g1ad[h * 256 + f];
        s  = fmaf(x.x, ws.x, fmaf(x.y, ws.y, fmaf(x.z, ws.z, fmaf(x.w, ws.w, s))));
        ds = fmaf(x.x, wd.x, fmaf(x.y, wd.y, fmaf(x.z, wd.z, fmaf(x.w, wd.w, ds))));
    }
    #pragma unroll
    for (int o = 16; o > 0; o >>= 1) {
        s  += __shfl_down_sync(0xffffffffu, s, o);
        ds += __shfl_down_sync(0xffffffffu, ds, o);
    }
    if (lane == 0) { g_asrc[n * 4 + h] = s; g_adst[n * 4 + h] = ds; }
}

// ---------------- GAT1 aggregate -> h1, regin ----------------
__global__ void gat1_kernel(const float* __restrict__ g1b,
                            const float* __restrict__ boxes) {
    __shared__ float alpha[KNB * 4];
    __shared__ int nb[KNB];
    const int n = blockIdx.x, tid = threadIdx.x;    // 256 threads
    if (tid < KNB) nb[tid] = g_nbr[n * KNB + tid];
    __syncthreads();
    if (tid < 4) {
        int h = tid;
        float ad = g_adst[n * 4 + h];
        float lg[KNB]; float mx = -3.4e38f;
        #pragma unroll
        for (int k = 0; k < KNB; k++) {
            float v = g_asrc[nb[k] * 4 + h] + ad;
            v = (v > 0.f) ? v : 0.2f * v;
            lg[k] = v; mx = fmaxf(mx, v);
        }
        float ssum = 0.f;
        #pragma unroll
        for (int k = 0; k < KNB; k++) { lg[k] = __expf(lg[k] - mx); ssum += lg[k]; }
        float inv = 1.0f / ssum;
        #pragma unroll
        for (int k = 0; k < KNB; k++) alpha[k * 4 + h] = lg[k] * inv;
    }
    __syncthreads();
    const int c4 = tid * 4, h = c4 >> 8;
    float4 acc = make_float4(0.f, 0.f, 0.f, 0.f);
    #pragma unroll
    for (int k = 0; k < KNB; k++) {
        float a = alpha[k * 4 + h];
        float4 x = *(const float4*)&g_xp[nb[k] * 1024 + c4];
        acc.x = fmaf(a, x.x, acc.x); acc.y = fmaf(a, x.y, acc.y);
        acc.z = fmaf(a, x.z, acc.z); acc.w = fmaf(a, x.w, acc.w);
    }
    float4 b4 = *(const float4*)&g1b[c4];
    float4 v = make_float4(fmaxf(acc.x + b4.x, 0.f), fmaxf(acc.y + b4.y, 0.f),
                           fmaxf(acc.z + b4.z, 0.f), fmaxf(acc.w + b4.w, 0.f));
    *(float4*)&g_h1[n * 1024 + c4] = v;
    *(float4*)&g_regin[n * XP + c4] = v;
    if (tid < 4) g_regin[n * XP + 1024 + tid] = boxes[n * 4 + tid] * (1.0f / 800.0f);
}

// ---------------- thin GEMM: hid = relu(regin @ rW1p + rb1), 8 rows/block ----------------
__global__ __launch_bounds__(256) void thin_gemm(const float* __restrict__ bias,
                                                 float* __restrict__ C) {
    __shared__ float Bs[32][128];
    __shared__ float As[8][32];
    __shared__ float red[8][128];
    const int tid = threadIdx.x;
    const int row0 = blockIdx.x * 8;
    const int g = tid >> 7, col = tid & 127;
    float acc[8];
    #pragma unroll
    for (int r = 0; r < 8; r++) acc[r] = 0.f;

    for (int k0 = 0; k0 < XP; k0 += 32) {
        __syncthreads();
        #pragma unroll
        for (int i = 0; i < 4; i++) {
            int idx = tid + i * 256;
            int r = idx >> 5, c4 = (idx & 31) * 4;
            *(float4*)&Bs[r][c4] = *(const float4*)&g_rW1p[(k0 + r) * 128 + c4];
        }
        if (tid < 64) {
            int r = tid >> 3, c4 = (tid & 7) * 4;
            *(float4*)&As[r][c4] = *(const float4*)&g_regin[(row0 + r) * XP + k0 + c4];
        }
        __syncthreads();
        #pragma unroll
        for (int kk = 0; kk < 16; kk++) {
            int k = g * 16 + kk;
            float b = Bs[k][col];
            #pragma unroll
            for (int r = 0; r < 8; r++) acc[r] = fmaf(As[r][k], b, acc[r]);
        }
    }
    __syncthreads();
    if (g == 1) {
        #pragma unroll
        for (int r = 0; r < 8; r++) red[r][col] = acc[r];
    }
    __syncthreads();
    if (g == 0) {
        float bb = bias[col];
        #pragma unroll
        for (int r = 0; r < 8; r++) {
            float v = fmaxf(acc[r] + red[r][col] + bb, 0.f);
            C[(row0 + r) * 128 + col] = v;
        }
    }
}

// ---------------- GAT2 projection + coefficients ----------------
__global__ void gat2_proj_kernel(const float* __restrict__ g2W,
                                 const float* __restrict__ g2as,
                                 const float* __restrict__ g2ad) {
    __shared__ float s0[256], s1[256];
    const int n = blockIdx.x, tid = threadIdx.x;    // 256
    float4 hv = *(const float4*)&g_h1[n * 1024 + tid * 4];
    float4 w0 = *(const float4*)&g2W[tid * 8];
    float4 w1 = *(const float4*)&g2W[tid * 8 + 4];
    float a0 = hv.x * w0.x + hv.y * w0.z + hv.z * w1.x + hv.w * w1.z;
    float a1 = hv.x * w0.y + hv.y * w0.w + hv.z * w1.y + hv.w * w1.w;
    s0[tid] = a0; s1[tid] = a1;
    __syncthreads();
    for (int o = 128; o > 0; o >>= 1) {
        if (tid < o) { s0[tid] += s0[tid + o]; s1[tid] += s1[tid + o]; }
        __syncthreads();
    }
    if (tid == 0) {
        float x0 = s0[0], x1 = s1[0];
        g_xp2[n * 2 + 0] = x0; g_xp2[n * 2 + 1] = x1;
        g_a2s[n] = x0 * g2as[0] + x1 * g2as[1];
        g_a2d[n] = x0 * g2ad[0] + x1 * g2ad[1];
    }
}

// ---------------- final: GAT2 aggregate + reg head + box decode ----------------
__global__ void final_kernel(const float* __restrict__ g2b,
                             const float* __restrict__ rW2,
                             const float* __restrict__ rb2,
                             const float* __restrict__ boxes,
                             float* __restrict__ out) {
    __shared__ float delta[4];
    const int n = blockIdx.x, tid = threadIdx.x;    // 128 threads
    const int c = tid >> 5, lane = tid & 31;
    float acc = 0.f;
    for (int i = lane; i < 128; i += 32)
        acc = fmaf(g_hid[n * 128 + i], rW2[i * 4 + c], acc);
    #pragma unroll
    for (int o = 16; o > 0; o >>= 1) acc += __shfl_down_sync(0xffffffffu, acc, o);
    if (lane == 0) delta[c] = acc + rb2[c];
    __syncthreads();
    if (tid == 0) {
        float ad = g_a2d[n];
        float lg[KNB]; float mx = -3.4e38f;
        int nb[KNB];
        #pragma unroll
        for (int k = 0; k < KNB; k++) nb[k] = g_nbr[n * KNB + k];
        #pragma unroll
        for (int k = 0; k < KNB; k++) {
            float v = g_a2s[nb[k]] + ad;
            v = (v > 0.f) ? v : 0.2f * v;
            lg[k] = v; mx = fmaxf(mx, v);
        }
        float ssum = 0.f;
        #pragma unroll
        for (int k = 0; k < KNB; k++) { lg[k] = expf(lg[k] - mx); ssum += lg[k]; }
        float inv = 1.0f / ssum;
        float o0 = 0.f, o1 = 0.f;
        #pragma unroll
        for (int k = 0; k < KNB; k++) {
            float a = lg[k] * inv;
            o0 = fmaf(a, g_xp2[nb[k] * 2 + 0], o0);
            o1 = fmaf(a, g_xp2[nb[k] * 2 + 1], o1);
        }
        out[n * 6 + 0] = o0 + g2b[0];
        out[n * 6 + 1] = o1 + g2b[1];
        float x0 = boxes[n * 4 + 0], y0 = boxes[n * 4 + 1];
        float x1 = boxes[n * 4 + 2], y1 = boxes[n * 4 + 3];
        float pw = x1 - x0, ph = y1 - y0;
        float pcx = x0 + 0.5f * pw, pcy = y0 + 0.5f * ph;
        float gcx = delta[0] * pw + pcx, gcy = delta[1] * ph + pcy;
        float gw = expf(delta[2]) * pw, gh = expf(delta[3]) * ph;
        out[n * 6 + 2] = gcx - 0.5f * gw;
        out[n * 6 + 3] = gcy - 0.5f * gh;
        out[n * 6 + 4] = gcx + 0.5f * gw;
        out[n * 6 + 5] = gcy + 0.5f * gh;
    }
}

// ---------------- launch ----------------
extern "C" void kernel_launch(void* const* d_in, const int* in_sizes, int n_in,
                              void* d_out, int out_size) {
    const float* feats = (const float*)d_in[0];
    const float* boxes = (const float*)d_in[1];
    const float* W1    = (const float*)d_in[2];
    const float* b1    = (const float*)d_in[3];
    const float* W2    = (const float*)d_in[4];
    const float* b2    = (const float*)d_in[5];
    const float* g1W   = (const float*)d_in[6];
    const float* g1as  = (const float*)d_in[7];
    const float* g1ad  = (const float*)d_in[8];
    const float* g1b   = (const float*)d_in[9];
    const float* g2W   = (const float*)d_in[10];
    const float* g2as  = (const float*)d_in[11];
    const float* g2ad  = (const float*)d_in[12];
    const float* g2b   = (const float*)d_in[13];
    const float* rW1   = (const float*)d_in[14];
    const float* rb1   = (const float*)d_in[15];
    const float* rW2   = (const float*)d_in[16];
    const float* rb2   = (const float*)d_in[17];
    float* out = (float*)d_out;

    float *pRel, *pHid;
    int *pNbr;
    cudaGetSymbolAddress((void**)&pRel, g_rel);
    cudaGetSymbolAddress((void**)&pNbr, g_nbr);
    cudaGetSymbolAddress((void**)&pHid, g_hid);

    pack_kernel<<<256, 256>>>(feats, boxes, W1, g1W, rW1);
    mega_gemm<<<288, 256>>>(feats);
    rel_kernel<<<dim3(24, 24), dim3(32, 8)>>>(boxes, W1, b1, W2, b2, pRel);
    topk_warp<<<96, 256>>>(pRel, pNbr);
    attn_coef_kernel<<<NNODES, 128>>>(g1as, g1ad);
    gat1_kernel<<<NNODES, 256>>>(g1b, boxes);
    thin_gemm<<<96, 256>>>(rb1, pHid);
    gat2_proj_kernel<<<NNODES, 256>>>(g2W, g2as, g2ad);
    final_kernel<<<NNODES, 128>>>(g2b, rW2, rb2, boxes, out);
}